// round 4
// baseline (speedup 1.0000x reference)
#include <cuda_runtime.h>
#include <cuda_bf16.h>
#include <cstdint>

#define N_NODES 100000
#define N_EDGES 600000
#define HID 128
#define OUT 24

// ---------------- scratch ----------------
__device__ float g_h  [(size_t)N_NODES * HID];
__device__ float g_agg[(size_t)N_NODES * HID];
__device__ float g_hid[(size_t)N_NODES * HID];
__device__ int   g_deg [N_NODES];
__device__ int   g_off [N_NODES + 1];
__device__ int   g_cur [N_NODES];
__device__ int   g_perm[N_EDGES];

// ---------------- packed f32x2 helpers ----------------
__device__ __forceinline__ unsigned long long pk2(float lo, float hi) {
    unsigned long long r;
    asm("mov.b64 %0, {%1, %2};" : "=l"(r) : "f"(lo), "f"(hi));
    return r;
}
__device__ __forceinline__ void fma2(unsigned long long& d,
                                     unsigned long long a, unsigned long long b) {
    asm("fma.rn.f32x2 %0, %1, %2, %0;" : "+l"(d) : "l"(a), "l"(b));
}
__device__ __forceinline__ float2 upk(unsigned long long v) {
    float2 f;
    asm("mov.b64 {%0, %1}, %2;" : "=f"(f.x), "=f"(f.y) : "l"(v));
    return f;
}

// ---------------- SGEMM (R2 version): C=A@W(+bias)(+relu), N==128 ---------
#define BM 128
#define BN 128
#define BK 16

template<bool RELU>
__global__ __launch_bounds__(256)
void sgemm_kernel(const float* __restrict__ A, int lda,
                  const float* __restrict__ W, int ldw,
                  const float* __restrict__ bias,
                  float* __restrict__ C, int ldc,
                  int M, int K)
{
    __shared__ float As[BK][BM];
    __shared__ float Ws[BK][BN];

    const int tid = threadIdx.x;
    const int m0 = blockIdx.y * BM;
    const int tx = tid & 15;
    const int ty = tid >> 4;

    unsigned long long acc2[8][4];
    #pragma unroll
    for (int i = 0; i < 8; i++)
        #pragma unroll
        for (int j = 0; j < 4; j++) acc2[i][j] = 0ull;

    for (int k0 = 0; k0 < K; k0 += BK) {
        #pragma unroll
        for (int p = 0; p < 2; p++) {
            int idx = tid + p * 256;
            int m   = idx >> 2;
            int k4  = (idx & 3) << 2;
            float4 v = make_float4(0.f, 0.f, 0.f, 0.f);
            int gm = m0 + m;
            if (gm < M)
                v = *reinterpret_cast<const float4*>(A + (size_t)gm * lda + k0 + k4);
            As[k4 + 0][m] = v.x;
            As[k4 + 1][m] = v.y;
            As[k4 + 2][m] = v.z;
            As[k4 + 3][m] = v.w;
        }
        #pragma unroll
        for (int p = 0; p < 2; p++) {
            int idx = tid + p * 256;
            int k   = idx >> 5;
            int n4  = (idx & 31) << 2;
            *reinterpret_cast<float4*>(&Ws[k][n4]) =
                *reinterpret_cast<const float4*>(W + (size_t)(k0 + k) * ldw + n4);
        }
        __syncthreads();

        #pragma unroll
        for (int kk = 0; kk < BK; kk++) {
            float a[8];
            *reinterpret_cast<float4*>(&a[0]) = *reinterpret_cast<float4*>(&As[kk][ty * 8]);
            *reinterpret_cast<float4*>(&a[4]) = *reinterpret_cast<float4*>(&As[kk][ty * 8 + 4]);
            unsigned long long b2[4];
            const unsigned long long* bp =
                reinterpret_cast<const unsigned long long*>(&Ws[kk][tx * 8]);
            #pragma unroll
            for (int j = 0; j < 4; j++) b2[j] = bp[j];
            #pragma unroll
            for (int i = 0; i < 8; i++) {
                unsigned long long a2 = pk2(a[i], a[i]);
                #pragma unroll
                for (int j = 0; j < 4; j++)
                    fma2(acc2[i][j], a2, b2[j]);
            }
        }
        __syncthreads();
    }

    const int gn = tx * 8;
    float4 bia0 = make_float4(0.f,0.f,0.f,0.f), bia1 = bia0;
    if (bias) {
        bia0 = *reinterpret_cast<const float4*>(bias + gn);
        bia1 = *reinterpret_cast<const float4*>(bias + gn + 4);
    }
    #pragma unroll
    for (int i = 0; i < 8; i++) {
        int gm = m0 + ty * 8 + i;
        if (gm >= M) continue;
        float2 p0 = upk(acc2[i][0]), p1 = upk(acc2[i][1]);
        float2 p2 = upk(acc2[i][2]), p3 = upk(acc2[i][3]);
        float4 v0 = make_float4(p0.x + bia0.x, p0.y + bia0.y, p1.x + bia0.z, p1.y + bia0.w);
        float4 v1 = make_float4(p2.x + bia1.x, p2.y + bia1.y, p3.x + bia1.z, p3.y + bia1.w);
        if (RELU) {
            v0.x = fmaxf(v0.x, 0.f); v0.y = fmaxf(v0.y, 0.f);
            v0.z = fmaxf(v0.z, 0.f); v0.w = fmaxf(v0.w, 0.f);
            v1.x = fmaxf(v1.x, 0.f); v1.y = fmaxf(v1.y, 0.f);
            v1.z = fmaxf(v1.z, 0.f); v1.w = fmaxf(v1.w, 0.f);
        }
        float* cp = C + (size_t)gm * ldc + gn;
        *reinterpret_cast<float4*>(cp)     = v0;
        *reinterpret_cast<float4*>(cp + 4) = v1;
    }
}

// ---------------- small utility kernels ----------------
__global__ void copy_kernel(float4* __restrict__ dst, const float4* __restrict__ src, int n4)
{
    int i = blockIdx.x * blockDim.x + threadIdx.x;
    if (i < n4) dst[i] = src[i];
}

__global__ void zero_int_kernel(int* __restrict__ p, int n)
{
    int i = blockIdx.x * blockDim.x + threadIdx.x;
    if (i < n) p[i] = 0;
}

__global__ void hist_kernel(const int* __restrict__ dst, int* __restrict__ deg, int E)
{
    int e = blockIdx.x * blockDim.x + threadIdx.x;
    if (e < E) atomicAdd(&deg[dst[e]], 1);
}

// single-block 1024-thread prefix scan: off[i+1]=incl, cur[i]=excl, off[0]=0
__global__ __launch_bounds__(1024)
void scan_kernel(const int* __restrict__ deg, int* __restrict__ off,
                 int* __restrict__ cur, int n)
{
    __shared__ int wsum[32];
    __shared__ int carry_s;
    const int tid = threadIdx.x;
    const int lane = tid & 31, wid = tid >> 5;
    if (tid == 0) { carry_s = 0; off[0] = 0; }
    __syncthreads();
    for (int base = 0; base < n; base += 1024) {
        int i = base + tid;
        int v = (i < n) ? deg[i] : 0;
        int x = v;
        #pragma unroll
        for (int o = 1; o < 32; o <<= 1) {
            int y = __shfl_up_sync(0xffffffff, x, o);
            if (lane >= o) x += y;
        }
        if (lane == 31) wsum[wid] = x;
        __syncthreads();
        if (wid == 0) {
            int s = wsum[lane];
            #pragma unroll
            for (int o = 1; o < 32; o <<= 1) {
                int y = __shfl_up_sync(0xffffffff, s, o);
                if (lane >= o) s += y;
            }
            wsum[lane] = s;
        }
        __syncthreads();
        int warp_off = (wid == 0) ? 0 : wsum[wid - 1];
        int incl = carry_s + warp_off + x;
        if (i < n) {
            off[i + 1] = incl;
            cur[i] = incl - v;
        }
        __syncthreads();
        if (tid == 0) carry_s += wsum[31];
        __syncthreads();
    }
}

__global__ void fill_kernel(const int* __restrict__ dst, int* __restrict__ cur,
                            int* __restrict__ perm, int E)
{
    int e = blockIdx.x * blockDim.x + threadIdx.x;
    if (e < E) {
        int p = atomicAdd(&cur[dst[e]], 1);
        perm[p] = e;
    }
}

// ---------------- CSR gather: agg[n] = h[n] + sum_{e: dst=n} relu(h[src]+ea@ew+eb)
#define GNB 32   // nodes per block
#define GCH 64   // edge chunk in smem

__global__ __launch_bounds__(128)
void gather_kernel(const float* __restrict__ h,
                   const int* __restrict__ src,
                   const int* __restrict__ dst,
                   const float* __restrict__ ea,
                   const float* __restrict__ ew,
                   const float* __restrict__ eb,
                   const int* __restrict__ off,
                   const int* __restrict__ perm,
                   float* __restrict__ agg,
                   int NN)
{
    __shared__ float ea_s[GCH][32];
    __shared__ int perm_s[GCH];
    __shared__ int src_s[GCH];
    __shared__ int nid_s[GCH];

    const int d = threadIdx.x;
    unsigned long long wcol2[16];
    #pragma unroll
    for (int t = 0; t < 16; t++)
        wcol2[t] = pk2(ew[(2 * t) * HID + d], ew[(2 * t + 1) * HID + d]);
    const float bd = eb[d];

    const int n0 = blockIdx.x * GNB;
    const int n1 = min(n0 + GNB, NN);
    const int p0 = off[n0];
    const int p1 = off[n1];

    int cur = -1;
    float acc = 0.f;

    for (int c0 = p0; c0 < p1; c0 += GCH) {
        const int len = min(GCH, p1 - c0);
        __syncthreads();
        if (d < len) {
            int e = perm[c0 + d];
            perm_s[d] = e;
            src_s[d] = src[e];
            nid_s[d] = dst[e];
        }
        __syncthreads();
        for (int idx = d; idx < len * 32; idx += 128)
            ea_s[idx >> 5][idx & 31] = ea[(size_t)perm_s[idx >> 5] * 32 + (idx & 31)];
        __syncthreads();

        float hs = h[(size_t)src_s[0] * HID + d];
        for (int i = 0; i < len; i++) {
            float hs_next = 0.f;
            if (i + 1 < len) hs_next = h[(size_t)src_s[i + 1] * HID + d];
            int n = nid_s[i];
            if (n != cur) {
                if (cur >= 0)
                    agg[(size_t)cur * HID + d] = h[(size_t)cur * HID + d] + acc;
                cur = n;
                acc = 0.f;
            }
            const unsigned long long* eav =
                reinterpret_cast<const unsigned long long*>(&ea_s[i][0]);
            unsigned long long ac0 = 0ull, ac1 = 0ull;
            #pragma unroll
            for (int t = 0; t < 8; t++) {
                fma2(ac0, eav[2 * t],     wcol2[2 * t]);
                fma2(ac1, eav[2 * t + 1], wcol2[2 * t + 1]);
            }
            float2 s0 = upk(ac0), s1 = upk(ac1);
            acc += fmaxf((s0.x + s0.y) + (s1.x + s1.y) + bd + hs, 0.f);
            hs = hs_next;
        }
    }
    if (cur >= 0)
        agg[(size_t)cur * HID + d] = h[(size_t)cur * HID + d] + acc;
}

// ---------------- fused classifier (R2) ----------------
#define CLS_E 64
#define HPAD 132

__global__ __launch_bounds__(128)
void cls_fused_kernel(const float* __restrict__ P,
                      const float* __restrict__ Q,
                      const int* __restrict__ src,
                      const int* __restrict__ dst,
                      const float* __restrict__ ea,
                      const float* __restrict__ w1c,
                      const float* __restrict__ b1,
                      const float* __restrict__ w2,
                      const float* __restrict__ b2,
                      float* __restrict__ out,
                      int E)
{
    __shared__ float hid_s[CLS_E][HPAD];
    __shared__ float w2t[OUT][HPAD];
    __shared__ float ea_s[CLS_E][32];
    __shared__ int src_s[CLS_E];
    __shared__ int dst_s[CLS_E];

    const int tid = threadIdx.x;
    const int base = blockIdx.x * CLS_E;
    const int ne = min(CLS_E, E - base);
    if (ne <= 0) return;

    for (int idx = tid; idx < HID * OUT; idx += 128) {
        float v = w2[idx];
        w2t[idx % OUT][idx / OUT] = v;
    }
    for (int idx = tid; idx < ne * 32; idx += 128)
        ea_s[idx >> 5][idx & 31] = ea[(size_t)base * 32 + idx];
    if (tid < ne) {
        src_s[tid] = src[base + tid];
        dst_s[tid] = dst[base + tid];
    }
    __syncthreads();

    {
        const int d = tid;
        unsigned long long wcol2[16];
        #pragma unroll
        for (int t = 0; t < 16; t++)
            wcol2[t] = pk2(w1c[(2 * t) * HID + d], w1c[(2 * t + 1) * HID + d]);
        const float bd = b1[d];

        float pq = P[(size_t)src_s[0] * HID + d] + Q[(size_t)dst_s[0] * HID + d];
        for (int e = 0; e < ne; e++) {
            float pq_next = 0.f;
            if (e + 1 < ne)
                pq_next = P[(size_t)src_s[e + 1] * HID + d] +
                          Q[(size_t)dst_s[e + 1] * HID + d];
            const unsigned long long* eav =
                reinterpret_cast<const unsigned long long*>(&ea_s[e][0]);
            unsigned long long ac0 = 0ull, ac1 = 0ull;
            #pragma unroll
            for (int t = 0; t < 8; t++) {
                fma2(ac0, eav[2 * t],     wcol2[2 * t]);
                fma2(ac1, eav[2 * t + 1], wcol2[2 * t + 1]);
            }
            float2 s0 = upk(ac0), s1 = upk(ac1);
            hid_s[e][d] = fmaxf((s0.x + s0.y) + (s1.x + s1.y) + bd + pq, 0.f);
            pq = pq_next;
        }
    }
    __syncthreads();

    const int oq = tid & 7;
    const int eq = tid >> 3;
    const int o0 = oq * 3;
    const int e0 = eq * 4;

    unsigned long long acc2[4][3];
    #pragma unroll
    for (int i = 0; i < 4; i++)
        #pragma unroll
        for (int j = 0; j < 3; j++) acc2[i][j] = 0ull;

    #pragma unroll 4
    for (int dch = 0; dch < HID; dch += 4) {
        unsigned long long h2[4][2], w2r[3][2];
        #pragma unroll
        for (int i = 0; i < 4; i++) {
            const unsigned long long* hp =
                reinterpret_cast<const unsigned long long*>(&hid_s[e0 + i][dch]);
            h2[i][0] = hp[0]; h2[i][1] = hp[1];
        }
        #pragma unroll
        for (int j = 0; j < 3; j++) {
            const unsigned long long* wp =
                reinterpret_cast<const unsigned long long*>(&w2t[o0 + j][dch]);
            w2r[j][0] = wp[0]; w2r[j][1] = wp[1];
        }
        #pragma unroll
        for (int i = 0; i < 4; i++)
            #pragma unroll
            for (int j = 0; j < 3; j++) {
                fma2(acc2[i][j], h2[i][0], w2r[j][0]);
                fma2(acc2[i][j], h2[i][1], w2r[j][1]);
            }
    }

    #pragma unroll
    for (int i = 0; i < 4; i++) {
        int e = e0 + i;
        if (e >= ne) continue;
        #pragma unroll
        for (int j = 0; j < 3; j++) {
            float2 s = upk(acc2[i][j]);
            out[(size_t)(base + e) * OUT + o0 + j] = s.x + s.y + b2[o0 + j];
        }
    }
}

// ---------------- host ----------------
extern "C" void kernel_launch(void* const* d_in, const int* in_sizes, int n_in,
                              void* d_out, int out_size)
{
    const float* x      = (const float*)d_in[0];
    const int*   eidx   = (const int*)  d_in[1];
    const float* ea     = (const float*)d_in[2];
    const float* lin1_w = (const float*)d_in[3];
    const float* lin1_b = (const float*)d_in[4];
    const float* cls_w1 = (const float*)d_in[23];
    const float* cls_b1 = (const float*)d_in[24];
    const float* cls_w2 = (const float*)d_in[25];
    const float* cls_b2 = (const float*)d_in[26];

    const int NN = in_sizes[0] / 64;
    const int E  = in_sizes[2] / 32;
    const int* src = eidx;
    const int* dst = eidx + E;

    float *h, *agg, *hid;
    int *deg, *off, *cur, *perm;
    cudaGetSymbolAddress((void**)&h,    g_h);
    cudaGetSymbolAddress((void**)&agg,  g_agg);
    cudaGetSymbolAddress((void**)&hid,  g_hid);
    cudaGetSymbolAddress((void**)&deg,  g_deg);
    cudaGetSymbolAddress((void**)&off,  g_off);
    cudaGetSymbolAddress((void**)&cur,  g_cur);
    cudaGetSymbolAddress((void**)&perm, g_perm);

    const dim3 gnode(1, (unsigned)((NN + BM - 1) / BM));
    const int cblocks = (E + CLS_E - 1) / CLS_E;
    const int gblocks = (NN + GNB - 1) / GNB;
    const int copy_n4 = (NN * HID) / 4;
    const int copy_blocks = (copy_n4 + 255) / 256;

    // ---- CSR build (once; reused by all 3 layers) ----
    zero_int_kernel<<<(NN + 255) / 256, 256>>>(deg, NN);
    hist_kernel<<<(E + 255) / 256, 256>>>(dst, deg, E);
    scan_kernel<<<1, 1024>>>(deg, off, cur, NN);
    fill_kernel<<<(E + 255) / 256, 256>>>(dst, cur, perm, E);

    // h = x @ lin1_w + lin1_b
    sgemm_kernel<false><<<gnode, 256>>>(x, 64, lin1_w, HID, lin1_b, h, HID, NN, 64);

    for (int c = 0; c < 3; c++) {
        const float* ew = (const float*)d_in[5 + 6 * c];
        const float* eb = (const float*)d_in[6 + 6 * c];
        const float* w1 = (const float*)d_in[7 + 6 * c];
        const float* b1 = (const float*)d_in[8 + 6 * c];
        const float* w2 = (const float*)d_in[9 + 6 * c];
        const float* b2 = (const float*)d_in[10 + 6 * c];

        // cover zero-in-degree nodes; gather overwrites nodes with edges
        copy_kernel<<<copy_blocks, 256>>>((float4*)agg, (const float4*)h, copy_n4);
        gather_kernel<<<gblocks, 128>>>(h, src, dst, ea, ew, eb, off, perm, agg, NN);
        sgemm_kernel<true><<<gnode, 256>>>(agg, HID, w1, HID, b1, hid, HID, NN, HID);
        sgemm_kernel<true><<<gnode, 256>>>(hid, HID, w2, HID, b2, h, HID, NN, HID);
    }

    sgemm_kernel<false><<<gnode, 256>>>(h, HID, cls_w1, HID, nullptr, hid, HID, NN, HID);
    sgemm_kernel<false><<<gnode, 256>>>(h, HID, cls_w1 + 128 * HID, HID, nullptr, agg, HID, NN, HID);

    cls_fused_kernel<<<cblocks, 128>>>(hid, agg, src, dst, ea,
                                       cls_w1 + 256 * HID, cls_b1,
                                       cls_w2, cls_b2, (float*)d_out, E);
}

// round 5
// speedup vs baseline: 1.0559x; 1.0559x over previous
#include <cuda_runtime.h>
#include <cuda_bf16.h>
#include <cstdint>

#define N_NODES 100000
#define N_EDGES 600000
#define HID 128
#define OUT 24

// ---------------- scratch ----------------
__device__ float g_h  [(size_t)N_NODES * HID];
__device__ float g_agg[(size_t)N_NODES * HID];
__device__ float g_hid[(size_t)N_NODES * HID];
__device__ int   g_deg [N_NODES];
__device__ int   g_off [N_NODES + 1];
__device__ int   g_cur [N_NODES];
__device__ int   g_perm[N_EDGES];

// ---------------- packed f32x2 helpers ----------------
__device__ __forceinline__ unsigned long long pk2(float lo, float hi) {
    unsigned long long r;
    asm("mov.b64 %0, {%1, %2};" : "=l"(r) : "f"(lo), "f"(hi));
    return r;
}
__device__ __forceinline__ void fma2(unsigned long long& d,
                                     unsigned long long a, unsigned long long b) {
    asm("fma.rn.f32x2 %0, %1, %2, %0;" : "+l"(d) : "l"(a), "l"(b));
}
__device__ __forceinline__ float2 upk(unsigned long long v) {
    float2 f;
    asm("mov.b64 {%0, %1}, %2;" : "=f"(f.x), "=f"(f.y) : "l"(v));
    return f;
}

// ---------------- SGEMM with register-staged prefetch ----------------------
#define BM 128
#define BN 128
#define BK 16

template<bool RELU>
__global__ __launch_bounds__(256)
void sgemm_kernel(const float* __restrict__ A, int lda,
                  const float* __restrict__ W, int ldw,
                  const float* __restrict__ bias,
                  float* __restrict__ C, int ldc,
                  int M, int K)
{
    __shared__ float As[BK][BM];
    __shared__ float Ws[BK][BN];

    const int tid = threadIdx.x;
    const int m0 = blockIdx.y * BM;
    const int tx = tid & 15;
    const int ty = tid >> 4;

    // A-load lane mapping (two chunks)
    const int a_m0 = tid >> 2;
    const int a_k4 = (tid & 3) << 2;
    // W-load lane mapping
    const int w_k0 = tid >> 5;
    const int w_n4 = (tid & 31) << 2;

    unsigned long long acc2[8][4];
    #pragma unroll
    for (int i = 0; i < 8; i++)
        #pragma unroll
        for (int j = 0; j < 4; j++) acc2[i][j] = 0ull;

    float4 ra[2], rw[2];

    auto load_tile = [&](int k0) {
        #pragma unroll
        for (int p = 0; p < 2; p++) {
            int gm = m0 + a_m0 + p * 64;
            ra[p] = make_float4(0.f, 0.f, 0.f, 0.f);
            if (gm < M)
                ra[p] = *reinterpret_cast<const float4*>(A + (size_t)gm * lda + k0 + a_k4);
            rw[p] = *reinterpret_cast<const float4*>(W + (size_t)(k0 + w_k0 + p * 8) * ldw + w_n4);
        }
    };
    auto store_tile = [&]() {
        #pragma unroll
        for (int p = 0; p < 2; p++) {
            int m = a_m0 + p * 64;
            As[a_k4 + 0][m] = ra[p].x;
            As[a_k4 + 1][m] = ra[p].y;
            As[a_k4 + 2][m] = ra[p].z;
            As[a_k4 + 3][m] = ra[p].w;
            *reinterpret_cast<float4*>(&Ws[w_k0 + p * 8][w_n4]) = rw[p];
        }
    };

    load_tile(0);
    for (int k0 = 0; k0 < K; k0 += BK) {
        store_tile();
        __syncthreads();
        if (k0 + BK < K) load_tile(k0 + BK);

        #pragma unroll
        for (int kk = 0; kk < BK; kk++) {
            float a[8];
            *reinterpret_cast<float4*>(&a[0]) = *reinterpret_cast<float4*>(&As[kk][ty * 8]);
            *reinterpret_cast<float4*>(&a[4]) = *reinterpret_cast<float4*>(&As[kk][ty * 8 + 4]);
            unsigned long long b2[4];
            const unsigned long long* bp =
                reinterpret_cast<const unsigned long long*>(&Ws[kk][tx * 8]);
            #pragma unroll
            for (int j = 0; j < 4; j++) b2[j] = bp[j];
            #pragma unroll
            for (int i = 0; i < 8; i++) {
                unsigned long long a2 = pk2(a[i], a[i]);
                #pragma unroll
                for (int j = 0; j < 4; j++)
                    fma2(acc2[i][j], a2, b2[j]);
            }
        }
        __syncthreads();
    }

    const int gn = tx * 8;
    float4 bia0 = make_float4(0.f,0.f,0.f,0.f), bia1 = bia0;
    if (bias) {
        bia0 = *reinterpret_cast<const float4*>(bias + gn);
        bia1 = *reinterpret_cast<const float4*>(bias + gn + 4);
    }
    #pragma unroll
    for (int i = 0; i < 8; i++) {
        int gm = m0 + ty * 8 + i;
        if (gm >= M) continue;
        float2 p0 = upk(acc2[i][0]), p1 = upk(acc2[i][1]);
        float2 p2 = upk(acc2[i][2]), p3 = upk(acc2[i][3]);
        float4 v0 = make_float4(p0.x + bia0.x, p0.y + bia0.y, p1.x + bia0.z, p1.y + bia0.w);
        float4 v1 = make_float4(p2.x + bia1.x, p2.y + bia1.y, p3.x + bia1.z, p3.y + bia1.w);
        if (RELU) {
            v0.x = fmaxf(v0.x, 0.f); v0.y = fmaxf(v0.y, 0.f);
            v0.z = fmaxf(v0.z, 0.f); v0.w = fmaxf(v0.w, 0.f);
            v1.x = fmaxf(v1.x, 0.f); v1.y = fmaxf(v1.y, 0.f);
            v1.z = fmaxf(v1.z, 0.f); v1.w = fmaxf(v1.w, 0.f);
        }
        float* cp = C + (size_t)gm * ldc + gn;
        *reinterpret_cast<float4*>(cp)     = v0;
        *reinterpret_cast<float4*>(cp + 4) = v1;
    }
}

// ---------------- small utility kernels ----------------
__global__ void copy_kernel(float4* __restrict__ dst, const float4* __restrict__ src, int n4)
{
    int i = blockIdx.x * blockDim.x + threadIdx.x;
    if (i < n4) dst[i] = src[i];
}

__global__ void zero_int_kernel(int* __restrict__ p, int n)
{
    int i = blockIdx.x * blockDim.x + threadIdx.x;
    if (i < n) p[i] = 0;
}

__global__ void hist_kernel(const int* __restrict__ dst, int* __restrict__ deg, int E)
{
    int e = blockIdx.x * blockDim.x + threadIdx.x;
    if (e < E) atomicAdd(&deg[dst[e]], 1);
}

__global__ __launch_bounds__(1024)
void scan_kernel(const int* __restrict__ deg, int* __restrict__ off,
                 int* __restrict__ cur, int n)
{
    __shared__ int wsum[32];
    __shared__ int carry_s;
    const int tid = threadIdx.x;
    const int lane = tid & 31, wid = tid >> 5;
    if (tid == 0) { carry_s = 0; off[0] = 0; }
    __syncthreads();
    for (int base = 0; base < n; base += 1024) {
        int i = base + tid;
        int v = (i < n) ? deg[i] : 0;
        int x = v;
        #pragma unroll
        for (int o = 1; o < 32; o <<= 1) {
            int y = __shfl_up_sync(0xffffffff, x, o);
            if (lane >= o) x += y;
        }
        if (lane == 31) wsum[wid] = x;
        __syncthreads();
        if (wid == 0) {
            int s = wsum[lane];
            #pragma unroll
            for (int o = 1; o < 32; o <<= 1) {
                int y = __shfl_up_sync(0xffffffff, s, o);
                if (lane >= o) s += y;
            }
            wsum[lane] = s;
        }
        __syncthreads();
        int warp_off = (wid == 0) ? 0 : wsum[wid - 1];
        int incl = carry_s + warp_off + x;
        if (i < n) {
            off[i + 1] = incl;
            cur[i] = incl - v;
        }
        __syncthreads();
        if (tid == 0) carry_s += wsum[31];
        __syncthreads();
    }
}

__global__ void fill_kernel(const int* __restrict__ dst, int* __restrict__ cur,
                            int* __restrict__ perm, int E)
{
    int e = blockIdx.x * blockDim.x + threadIdx.x;
    if (e < E) {
        int p = atomicAdd(&cur[dst[e]], 1);
        perm[p] = e;
    }
}

// ---------------- merged edge scatter (dst-sorted order) -------------------
// R2 structure: 128 threads, 32 edges/block — but edges come via perm (sorted
// by dst), and consecutive same-dst messages merge in a register before one
// atomicAdd flush per run.
__global__ __launch_bounds__(128)
void edge_scatter_kernel(const float* __restrict__ h,
                         const int* __restrict__ src,
                         const int* __restrict__ dst,
                         const float* __restrict__ ea,
                         const float* __restrict__ ew,
                         const float* __restrict__ eb,
                         const int* __restrict__ perm,
                         float* __restrict__ agg,
                         int E)
{
    __shared__ float ea_s[32][32];
    __shared__ int perm_s[32];
    __shared__ int src_s[32];
    __shared__ int dst_s[32];

    const int d = threadIdx.x;
    unsigned long long wcol2[16];
    #pragma unroll
    for (int t = 0; t < 16; t++)
        wcol2[t] = pk2(ew[(2 * t) * HID + d], ew[(2 * t + 1) * HID + d]);
    const float bd = eb[d];

    const int base = blockIdx.x * 32;
    const int ne = min(32, E - base);
    if (ne <= 0) return;

    if (threadIdx.x < ne) {
        int p = perm[base + threadIdx.x];
        perm_s[threadIdx.x] = p;
        src_s[threadIdx.x] = src[p];
        dst_s[threadIdx.x] = dst[p];
    }
    __syncthreads();
    for (int idx = threadIdx.x; idx < ne * 32; idx += 128)
        ea_s[idx >> 5][idx & 31] = ea[(size_t)perm_s[idx >> 5] * 32 + (idx & 31)];
    __syncthreads();

    float hs = h[(size_t)src_s[0] * HID + d];
    float run = 0.f;
    for (int e = 0; e < ne; e++) {
        float hs_next = 0.f;
        if (e + 1 < ne) hs_next = h[(size_t)src_s[e + 1] * HID + d];
        const unsigned long long* eav =
            reinterpret_cast<const unsigned long long*>(&ea_s[e][0]);
        unsigned long long ac0 = 0ull, ac1 = 0ull;
        #pragma unroll
        for (int t = 0; t < 8; t++) {
            fma2(ac0, eav[2 * t],     wcol2[2 * t]);
            fma2(ac1, eav[2 * t + 1], wcol2[2 * t + 1]);
        }
        float2 s0 = upk(ac0), s1 = upk(ac1);
        run += fmaxf((s0.x + s0.y) + (s1.x + s1.y) + bd + hs, 0.f);
        bool flush = (e + 1 == ne) || (dst_s[e + 1] != dst_s[e]);
        if (flush) {
            atomicAdd(&agg[(size_t)dst_s[e] * HID + d], run);
            run = 0.f;
        }
        hs = hs_next;
    }
}

// ---------------- fused classifier (R2) ----------------
#define CLS_E 64
#define HPAD 132

__global__ __launch_bounds__(128)
void cls_fused_kernel(const float* __restrict__ P,
                      const float* __restrict__ Q,
                      const int* __restrict__ src,
                      const int* __restrict__ dst,
                      const float* __restrict__ ea,
                      const float* __restrict__ w1c,
                      const float* __restrict__ b1,
                      const float* __restrict__ w2,
                      const float* __restrict__ b2,
                      float* __restrict__ out,
                      int E)
{
    __shared__ float hid_s[CLS_E][HPAD];
    __shared__ float w2t[OUT][HPAD];
    __shared__ float ea_s[CLS_E][32];
    __shared__ int src_s[CLS_E];
    __shared__ int dst_s[CLS_E];

    const int tid = threadIdx.x;
    const int base = blockIdx.x * CLS_E;
    const int ne = min(CLS_E, E - base);
    if (ne <= 0) return;

    for (int idx = tid; idx < HID * OUT; idx += 128) {
        float v = w2[idx];
        w2t[idx % OUT][idx / OUT] = v;
    }
    for (int idx = tid; idx < ne * 32; idx += 128)
        ea_s[idx >> 5][idx & 31] = ea[(size_t)base * 32 + idx];
    if (tid < ne) {
        src_s[tid] = src[base + tid];
        dst_s[tid] = dst[base + tid];
    }
    __syncthreads();

    {
        const int d = tid;
        unsigned long long wcol2[16];
        #pragma unroll
        for (int t = 0; t < 16; t++)
            wcol2[t] = pk2(w1c[(2 * t) * HID + d], w1c[(2 * t + 1) * HID + d]);
        const float bd = b1[d];

        float pq = P[(size_t)src_s[0] * HID + d] + Q[(size_t)dst_s[0] * HID + d];
        for (int e = 0; e < ne; e++) {
            float pq_next = 0.f;
            if (e + 1 < ne)
                pq_next = P[(size_t)src_s[e + 1] * HID + d] +
                          Q[(size_t)dst_s[e + 1] * HID + d];
            const unsigned long long* eav =
                reinterpret_cast<const unsigned long long*>(&ea_s[e][0]);
            unsigned long long ac0 = 0ull, ac1 = 0ull;
            #pragma unroll
            for (int t = 0; t < 8; t++) {
                fma2(ac0, eav[2 * t],     wcol2[2 * t]);
                fma2(ac1, eav[2 * t + 1], wcol2[2 * t + 1]);
            }
            float2 s0 = upk(ac0), s1 = upk(ac1);
            hid_s[e][d] = fmaxf((s0.x + s0.y) + (s1.x + s1.y) + bd + pq, 0.f);
            pq = pq_next;
        }
    }
    __syncthreads();

    const int oq = tid & 7;
    const int eq = tid >> 3;
    const int o0 = oq * 3;
    const int e0 = eq * 4;

    unsigned long long acc2[4][3];
    #pragma unroll
    for (int i = 0; i < 4; i++)
        #pragma unroll
        for (int j = 0; j < 3; j++) acc2[i][j] = 0ull;

    #pragma unroll 4
    for (int dch = 0; dch < HID; dch += 4) {
        unsigned long long h2[4][2], w2r[3][2];
        #pragma unroll
        for (int i = 0; i < 4; i++) {
            const unsigned long long* hp =
                reinterpret_cast<const unsigned long long*>(&hid_s[e0 + i][dch]);
            h2[i][0] = hp[0]; h2[i][1] = hp[1];
        }
        #pragma unroll
        for (int j = 0; j < 3; j++) {
            const unsigned long long* wp =
                reinterpret_cast<const unsigned long long*>(&w2t[o0 + j][dch]);
            w2r[j][0] = wp[0]; w2r[j][1] = wp[1];
        }
        #pragma unroll
        for (int i = 0; i < 4; i++)
            #pragma unroll
            for (int j = 0; j < 3; j++) {
                fma2(acc2[i][j], h2[i][0], w2r[j][0]);
                fma2(acc2[i][j], h2[i][1], w2r[j][1]);
            }
    }

    #pragma unroll
    for (int i = 0; i < 4; i++) {
        int e = e0 + i;
        if (e >= ne) continue;
        #pragma unroll
        for (int j = 0; j < 3; j++) {
            float2 s = upk(acc2[i][j]);
            out[(size_t)(base + e) * OUT + o0 + j] = s.x + s.y + b2[o0 + j];
        }
    }
}

// ---------------- host ----------------
extern "C" void kernel_launch(void* const* d_in, const int* in_sizes, int n_in,
                              void* d_out, int out_size)
{
    const float* x      = (const float*)d_in[0];
    const int*   eidx   = (const int*)  d_in[1];
    const float* ea     = (const float*)d_in[2];
    const float* lin1_w = (const float*)d_in[3];
    const float* lin1_b = (const float*)d_in[4];
    const float* cls_w1 = (const float*)d_in[23];
    const float* cls_b1 = (const float*)d_in[24];
    const float* cls_w2 = (const float*)d_in[25];
    const float* cls_b2 = (const float*)d_in[26];

    const int NN = in_sizes[0] / 64;
    const int E  = in_sizes[2] / 32;
    const int* src = eidx;
    const int* dst = eidx + E;

    float *h, *agg, *hid;
    int *deg, *off, *cur, *perm;
    cudaGetSymbolAddress((void**)&h,    g_h);
    cudaGetSymbolAddress((void**)&agg,  g_agg);
    cudaGetSymbolAddress((void**)&hid,  g_hid);
    cudaGetSymbolAddress((void**)&deg,  g_deg);
    cudaGetSymbolAddress((void**)&off,  g_off);
    cudaGetSymbolAddress((void**)&cur,  g_cur);
    cudaGetSymbolAddress((void**)&perm, g_perm);

    const dim3 gnode(1, (unsigned)((NN + BM - 1) / BM));
    const int sblocks = (E + 31) / 32;
    const int cblocks = (E + CLS_E - 1) / CLS_E;
    const int copy_n4 = (NN * HID) / 4;
    const int copy_blocks = (copy_n4 + 255) / 256;

    // ---- CSR build (once) ----
    zero_int_kernel<<<(NN + 255) / 256, 256>>>(deg, NN);
    hist_kernel<<<(E + 255) / 256, 256>>>(dst, deg, E);
    scan_kernel<<<1, 1024>>>(deg, off, cur, NN);
    fill_kernel<<<(E + 255) / 256, 256>>>(dst, cur, perm, E);

    sgemm_kernel<false><<<gnode, 256>>>(x, 64, lin1_w, HID, lin1_b, h, HID, NN, 64);

    for (int c = 0; c < 3; c++) {
        const float* ew = (const float*)d_in[5 + 6 * c];
        const float* eb = (const float*)d_in[6 + 6 * c];
        const float* w1 = (const float*)d_in[7 + 6 * c];
        const float* b1 = (const float*)d_in[8 + 6 * c];
        const float* w2 = (const float*)d_in[9 + 6 * c];
        const float* b2 = (const float*)d_in[10 + 6 * c];

        copy_kernel<<<copy_blocks, 256>>>((float4*)agg, (const float4*)h, copy_n4);
        edge_scatter_kernel<<<sblocks, 128>>>(h, src, dst, ea, ew, eb, perm, agg, E);
        sgemm_kernel<true><<<gnode, 256>>>(agg, HID, w1, HID, b1, hid, HID, NN, HID);
        sgemm_kernel<true><<<gnode, 256>>>(hid, HID, w2, HID, b2, h, HID, NN, HID);
    }

    sgemm_kernel<false><<<gnode, 256>>>(h, HID, cls_w1, HID, nullptr, hid, HID, NN, HID);
    sgemm_kernel<false><<<gnode, 256>>>(h, HID, cls_w1 + 128 * HID, HID, nullptr, agg, HID, NN, HID);

    cls_fused_kernel<<<cblocks, 128>>>(hid, agg, src, dst, ea,
                                       cls_w1 + 256 * HID, cls_b1,
                                       cls_w2, cls_b2, (float*)d_out, E);
}

// round 6
// speedup vs baseline: 1.1023x; 1.0440x over previous
#include <cuda_runtime.h>
#include <cuda_bf16.h>
#include <cstdint>

#define N_NODES 100000
#define N_EDGES 600000
#define HID 128
#define OUT 24

// ---------------- scratch ----------------
__device__ float g_h   [(size_t)N_NODES * HID];
__device__ float g_agg [(size_t)N_NODES * HID];
__device__ float g_hid [(size_t)N_NODES * HID];
__device__ float g_eas [(size_t)N_EDGES * 32];   // dst-sorted edge_attr
__device__ int   g_srcs[N_EDGES];                // dst-sorted src
__device__ int   g_dsts[N_EDGES];                // dst-sorted dst
__device__ int   g_deg [N_NODES];
__device__ int   g_off [N_NODES + 1];
__device__ int   g_cur [N_NODES];
__device__ int   g_perm[N_EDGES];

// ---------------- packed f32x2 helpers ----------------
__device__ __forceinline__ unsigned long long pk2(float lo, float hi) {
    unsigned long long r;
    asm("mov.b64 %0, {%1, %2};" : "=l"(r) : "f"(lo), "f"(hi));
    return r;
}
__device__ __forceinline__ void fma2(unsigned long long& d,
                                     unsigned long long a, unsigned long long b) {
    asm("fma.rn.f32x2 %0, %1, %2, %0;" : "+l"(d) : "l"(a), "l"(b));
}
__device__ __forceinline__ float2 upk(unsigned long long v) {
    float2 f;
    asm("mov.b64 {%0, %1}, %2;" : "=f"(f.x), "=f"(f.y) : "l"(v));
    return f;
}

// ---------------- SGEMM (exact R2 version): C=A@W(+bias)(+relu), N==128 ---
#define BM 128
#define BN 128
#define BK 16

template<bool RELU>
__global__ __launch_bounds__(256)
void sgemm_kernel(const float* __restrict__ A, int lda,
                  const float* __restrict__ W, int ldw,
                  const float* __restrict__ bias,
                  float* __restrict__ C, int ldc,
                  int M, int K)
{
    __shared__ float As[BK][BM];
    __shared__ float Ws[BK][BN];

    const int tid = threadIdx.x;
    const int m0 = blockIdx.y * BM;
    const int tx = tid & 15;
    const int ty = tid >> 4;

    unsigned long long acc2[8][4];
    #pragma unroll
    for (int i = 0; i < 8; i++)
        #pragma unroll
        for (int j = 0; j < 4; j++) acc2[i][j] = 0ull;

    for (int k0 = 0; k0 < K; k0 += BK) {
        #pragma unroll
        for (int p = 0; p < 2; p++) {
            int idx = tid + p * 256;
            int m   = idx >> 2;
            int k4  = (idx & 3) << 2;
            float4 v = make_float4(0.f, 0.f, 0.f, 0.f);
            int gm = m0 + m;
            if (gm < M)
                v = *reinterpret_cast<const float4*>(A + (size_t)gm * lda + k0 + k4);
            As[k4 + 0][m] = v.x;
            As[k4 + 1][m] = v.y;
            As[k4 + 2][m] = v.z;
            As[k4 + 3][m] = v.w;
        }
        #pragma unroll
        for (int p = 0; p < 2; p++) {
            int idx = tid + p * 256;
            int k   = idx >> 5;
            int n4  = (idx & 31) << 2;
            *reinterpret_cast<float4*>(&Ws[k][n4]) =
                *reinterpret_cast<const float4*>(W + (size_t)(k0 + k) * ldw + n4);
        }
        __syncthreads();

        #pragma unroll
        for (int kk = 0; kk < BK; kk++) {
            float a[8];
            *reinterpret_cast<float4*>(&a[0]) = *reinterpret_cast<float4*>(&As[kk][ty * 8]);
            *reinterpret_cast<float4*>(&a[4]) = *reinterpret_cast<float4*>(&As[kk][ty * 8 + 4]);
            unsigned long long b2[4];
            const unsigned long long* bp =
                reinterpret_cast<const unsigned long long*>(&Ws[kk][tx * 8]);
            #pragma unroll
            for (int j = 0; j < 4; j++) b2[j] = bp[j];
            #pragma unroll
            for (int i = 0; i < 8; i++) {
                unsigned long long a2 = pk2(a[i], a[i]);
                #pragma unroll
                for (int j = 0; j < 4; j++)
                    fma2(acc2[i][j], a2, b2[j]);
            }
        }
        __syncthreads();
    }

    const int gn = tx * 8;
    float4 bia0 = make_float4(0.f,0.f,0.f,0.f), bia1 = bia0;
    if (bias) {
        bia0 = *reinterpret_cast<const float4*>(bias + gn);
        bia1 = *reinterpret_cast<const float4*>(bias + gn + 4);
    }
    #pragma unroll
    for (int i = 0; i < 8; i++) {
        int gm = m0 + ty * 8 + i;
        if (gm >= M) continue;
        float2 p0 = upk(acc2[i][0]), p1 = upk(acc2[i][1]);
        float2 p2 = upk(acc2[i][2]), p3 = upk(acc2[i][3]);
        float4 v0 = make_float4(p0.x + bia0.x, p0.y + bia0.y, p1.x + bia0.z, p1.y + bia0.w);
        float4 v1 = make_float4(p2.x + bia1.x, p2.y + bia1.y, p3.x + bia1.z, p3.y + bia1.w);
        if (RELU) {
            v0.x = fmaxf(v0.x, 0.f); v0.y = fmaxf(v0.y, 0.f);
            v0.z = fmaxf(v0.z, 0.f); v0.w = fmaxf(v0.w, 0.f);
            v1.x = fmaxf(v1.x, 0.f); v1.y = fmaxf(v1.y, 0.f);
            v1.z = fmaxf(v1.z, 0.f); v1.w = fmaxf(v1.w, 0.f);
        }
        float* cp = C + (size_t)gm * ldc + gn;
        *reinterpret_cast<float4*>(cp)     = v0;
        *reinterpret_cast<float4*>(cp + 4) = v1;
    }
}

// ---------------- small utility kernels ----------------
__global__ void copy_kernel(float4* __restrict__ dst, const float4* __restrict__ src, int n4)
{
    int i = blockIdx.x * blockDim.x + threadIdx.x;
    if (i < n4) dst[i] = src[i];
}

__global__ void zero_int_kernel(int* __restrict__ p, int n)
{
    int i = blockIdx.x * blockDim.x + threadIdx.x;
    if (i < n) p[i] = 0;
}

__global__ void hist_kernel(const int* __restrict__ dst, int* __restrict__ deg, int E)
{
    int e = blockIdx.x * blockDim.x + threadIdx.x;
    if (e < E) atomicAdd(&deg[dst[e]], 1);
}

__global__ __launch_bounds__(1024)
void scan_kernel(const int* __restrict__ deg, int* __restrict__ off,
                 int* __restrict__ cur, int n)
{
    __shared__ int wsum[32];
    __shared__ int carry_s;
    const int tid = threadIdx.x;
    const int lane = tid & 31, wid = tid >> 5;
    if (tid == 0) { carry_s = 0; off[0] = 0; }
    __syncthreads();
    for (int base = 0; base < n; base += 1024) {
        int i = base + tid;
        int v = (i < n) ? deg[i] : 0;
        int x = v;
        #pragma unroll
        for (int o = 1; o < 32; o <<= 1) {
            int y = __shfl_up_sync(0xffffffff, x, o);
            if (lane >= o) x += y;
        }
        if (lane == 31) wsum[wid] = x;
        __syncthreads();
        if (wid == 0) {
            int s = wsum[lane];
            #pragma unroll
            for (int o = 1; o < 32; o <<= 1) {
                int y = __shfl_up_sync(0xffffffff, s, o);
                if (lane >= o) s += y;
            }
            wsum[lane] = s;
        }
        __syncthreads();
        int warp_off = (wid == 0) ? 0 : wsum[wid - 1];
        int incl = carry_s + warp_off + x;
        if (i < n) {
            off[i + 1] = incl;
            cur[i] = incl - v;
        }
        __syncthreads();
        if (tid == 0) carry_s += wsum[31];
        __syncthreads();
    }
}

__global__ void fill_kernel(const int* __restrict__ dst, int* __restrict__ cur,
                            int* __restrict__ perm, int E)
{
    int e = blockIdx.x * blockDim.x + threadIdx.x;
    if (e < E) {
        int p = atomicAdd(&cur[dst[e]], 1);
        perm[p] = e;
    }
}

// materialize dst-sorted edge arrays: eas[r]=ea[perm[r]], srcs[r]=src[perm[r]], dsts[r]=dst[perm[r]]
__global__ __launch_bounds__(128)
void permute_kernel(const int* __restrict__ perm,
                    const int* __restrict__ src,
                    const int* __restrict__ dst,
                    const float* __restrict__ ea,
                    float* __restrict__ eas,
                    int* __restrict__ srcs,
                    int* __restrict__ dsts,
                    int E)
{
    __shared__ int perm_s[32];
    const int base = blockIdx.x * 32;
    const int ne = min(32, E - base);
    if (ne <= 0) return;
    if (threadIdx.x < ne) {
        int p = perm[base + threadIdx.x];
        perm_s[threadIdx.x] = p;
        srcs[base + threadIdx.x] = src[p];
        dsts[base + threadIdx.x] = dst[p];
    }
    __syncthreads();
    // 32 edges x 8 float4 = 256 float4; 128 threads -> 2 each
    for (int idx = threadIdx.x; idx < ne * 8; idx += 128) {
        int e = idx >> 3;
        int q = idx & 7;
        float4 v = *reinterpret_cast<const float4*>(ea + (size_t)perm_s[e] * 32 + q * 4);
        *reinterpret_cast<float4*>(eas + (size_t)(base + e) * 32 + q * 4) = v;
    }
}

// ---------------- merged edge scatter on PRE-SORTED arrays -----------------
// Identical memory pattern to R2 (all sequential/coalesced), plus run-merged
// atomics: one atomicAdd per (node-run within block) instead of per edge.
__global__ __launch_bounds__(128)
void edge_scatter_kernel(const float* __restrict__ h,
                         const int* __restrict__ srcs,
                         const int* __restrict__ dsts,
                         const float* __restrict__ eas,
                         const float* __restrict__ ew,
                         const float* __restrict__ eb,
                         float* __restrict__ agg,
                         int E)
{
    __shared__ float ea_s[32][32];
    __shared__ int src_s[32];
    __shared__ int dst_s[32];

    const int d = threadIdx.x;
    unsigned long long wcol2[16];
    #pragma unroll
    for (int t = 0; t < 16; t++)
        wcol2[t] = pk2(ew[(2 * t) * HID + d], ew[(2 * t + 1) * HID + d]);
    const float bd = eb[d];

    const int base = blockIdx.x * 32;
    const int ne = min(32, E - base);
    if (ne <= 0) return;

    for (int idx = threadIdx.x; idx < ne * 32; idx += 128)
        ea_s[idx >> 5][idx & 31] = eas[(size_t)base * 32 + idx];
    if (threadIdx.x < ne) {
        src_s[threadIdx.x] = srcs[base + threadIdx.x];
        dst_s[threadIdx.x] = dsts[base + threadIdx.x];
    }
    __syncthreads();

    float hs = h[(size_t)src_s[0] * HID + d];
    float run = 0.f;
    for (int e = 0; e < ne; e++) {
        float hs_next = 0.f;
        if (e + 1 < ne) hs_next = h[(size_t)src_s[e + 1] * HID + d];
        const unsigned long long* eav =
            reinterpret_cast<const unsigned long long*>(&ea_s[e][0]);
        unsigned long long ac0 = 0ull, ac1 = 0ull;
        #pragma unroll
        for (int t = 0; t < 8; t++) {
            fma2(ac0, eav[2 * t],     wcol2[2 * t]);
            fma2(ac1, eav[2 * t + 1], wcol2[2 * t + 1]);
        }
        float2 s0 = upk(ac0), s1 = upk(ac1);
        run += fmaxf((s0.x + s0.y) + (s1.x + s1.y) + bd + hs, 0.f);
        bool flush = (e + 1 == ne) || (dst_s[e + 1] != dst_s[e]);
        if (flush) {
            atomicAdd(&agg[(size_t)dst_s[e] * HID + d], run);
            run = 0.f;
        }
        hs = hs_next;
    }
}

// ---------------- fused classifier (exact R2) ----------------
#define CLS_E 64
#define HPAD 132

__global__ __launch_bounds__(128)
void cls_fused_kernel(const float* __restrict__ P,
                      const float* __restrict__ Q,
                      const int* __restrict__ src,
                      const int* __restrict__ dst,
                      const float* __restrict__ ea,
                      const float* __restrict__ w1c,
                      const float* __restrict__ b1,
                      const float* __restrict__ w2,
                      const float* __restrict__ b2,
                      float* __restrict__ out,
                      int E)
{
    __shared__ float hid_s[CLS_E][HPAD];
    __shared__ float w2t[OUT][HPAD];
    __shared__ float ea_s[CLS_E][32];
    __shared__ int src_s[CLS_E];
    __shared__ int dst_s[CLS_E];

    const int tid = threadIdx.x;
    const int base = blockIdx.x * CLS_E;
    const int ne = min(CLS_E, E - base);
    if (ne <= 0) return;

    for (int idx = tid; idx < HID * OUT; idx += 128) {
        float v = w2[idx];
        w2t[idx % OUT][idx / OUT] = v;
    }
    for (int idx = tid; idx < ne * 32; idx += 128)
        ea_s[idx >> 5][idx & 31] = ea[(size_t)base * 32 + idx];
    if (tid < ne) {
        src_s[tid] = src[base + tid];
        dst_s[tid] = dst[base + tid];
    }
    __syncthreads();

    {
        const int d = tid;
        unsigned long long wcol2[16];
        #pragma unroll
        for (int t = 0; t < 16; t++)
            wcol2[t] = pk2(w1c[(2 * t) * HID + d], w1c[(2 * t + 1) * HID + d]);
        const float bd = b1[d];

        float pq = P[(size_t)src_s[0] * HID + d] + Q[(size_t)dst_s[0] * HID + d];
        for (int e = 0; e < ne; e++) {
            float pq_next = 0.f;
            if (e + 1 < ne)
                pq_next = P[(size_t)src_s[e + 1] * HID + d] +
                          Q[(size_t)dst_s[e + 1] * HID + d];
            const unsigned long long* eav =
                reinterpret_cast<const unsigned long long*>(&ea_s[e][0]);
            unsigned long long ac0 = 0ull, ac1 = 0ull;
            #pragma unroll
            for (int t = 0; t < 8; t++) {
                fma2(ac0, eav[2 * t],     wcol2[2 * t]);
                fma2(ac1, eav[2 * t + 1], wcol2[2 * t + 1]);
            }
            float2 s0 = upk(ac0), s1 = upk(ac1);
            hid_s[e][d] = fmaxf((s0.x + s0.y) + (s1.x + s1.y) + bd + pq, 0.f);
            pq = pq_next;
        }
    }
    __syncthreads();

    const int oq = tid & 7;
    const int eq = tid >> 3;
    const int o0 = oq * 3;
    const int e0 = eq * 4;

    unsigned long long acc2[4][3];
    #pragma unroll
    for (int i = 0; i < 4; i++)
        #pragma unroll
        for (int j = 0; j < 3; j++) acc2[i][j] = 0ull;

    #pragma unroll 4
    for (int dch = 0; dch < HID; dch += 4) {
        unsigned long long h2[4][2], w2r[3][2];
        #pragma unroll
        for (int i = 0; i < 4; i++) {
            const unsigned long long* hp =
                reinterpret_cast<const unsigned long long*>(&hid_s[e0 + i][dch]);
            h2[i][0] = hp[0]; h2[i][1] = hp[1];
        }
        #pragma unroll
        for (int j = 0; j < 3; j++) {
            const unsigned long long* wp =
                reinterpret_cast<const unsigned long long*>(&w2t[o0 + j][dch]);
            w2r[j][0] = wp[0]; w2r[j][1] = wp[1];
        }
        #pragma unroll
        for (int i = 0; i < 4; i++)
            #pragma unroll
            for (int j = 0; j < 3; j++) {
                fma2(acc2[i][j], h2[i][0], w2r[j][0]);
                fma2(acc2[i][j], h2[i][1], w2r[j][1]);
            }
    }

    #pragma unroll
    for (int i = 0; i < 4; i++) {
        int e = e0 + i;
        if (e >= ne) continue;
        #pragma unroll
        for (int j = 0; j < 3; j++) {
            float2 s = upk(acc2[i][j]);
            out[(size_t)(base + e) * OUT + o0 + j] = s.x + s.y + b2[o0 + j];
        }
    }
}

// ---------------- host ----------------
extern "C" void kernel_launch(void* const* d_in, const int* in_sizes, int n_in,
                              void* d_out, int out_size)
{
    const float* x      = (const float*)d_in[0];
    const int*   eidx   = (const int*)  d_in[1];
    const float* ea     = (const float*)d_in[2];
    const float* lin1_w = (const float*)d_in[3];
    const float* lin1_b = (const float*)d_in[4];
    const float* cls_w1 = (const float*)d_in[23];
    const float* cls_b1 = (const float*)d_in[24];
    const float* cls_w2 = (const float*)d_in[25];
    const float* cls_b2 = (const float*)d_in[26];

    const int NN = in_sizes[0] / 64;
    const int E  = in_sizes[2] / 32;
    const int* src = eidx;
    const int* dst = eidx + E;

    float *h, *agg, *hid, *eas;
    int *srcs, *dsts, *deg, *off, *cur, *perm;
    cudaGetSymbolAddress((void**)&h,    g_h);
    cudaGetSymbolAddress((void**)&agg,  g_agg);
    cudaGetSymbolAddress((void**)&hid,  g_hid);
    cudaGetSymbolAddress((void**)&eas,  g_eas);
    cudaGetSymbolAddress((void**)&srcs, g_srcs);
    cudaGetSymbolAddress((void**)&dsts, g_dsts);
    cudaGetSymbolAddress((void**)&deg,  g_deg);
    cudaGetSymbolAddress((void**)&off,  g_off);
    cudaGetSymbolAddress((void**)&cur,  g_cur);
    cudaGetSymbolAddress((void**)&perm, g_perm);

    const dim3 gnode(1, (unsigned)((NN + BM - 1) / BM));
    const int sblocks = (E + 31) / 32;
    const int cblocks = (E + CLS_E - 1) / CLS_E;
    const int copy_n4 = (NN * HID) / 4;
    const int copy_blocks = (copy_n4 + 255) / 256;

    // ---- CSR build + edge materialization (once) ----
    zero_int_kernel<<<(NN + 255) / 256, 256>>>(deg, NN);
    hist_kernel<<<(E + 255) / 256, 256>>>(dst, deg, E);
    scan_kernel<<<1, 1024>>>(deg, off, cur, NN);
    fill_kernel<<<(E + 255) / 256, 256>>>(dst, cur, perm, E);
    permute_kernel<<<sblocks, 128>>>(perm, src, dst, ea, eas, srcs, dsts, E);

    sgemm_kernel<false><<<gnode, 256>>>(x, 64, lin1_w, HID, lin1_b, h, HID, NN, 64);

    for (int c = 0; c < 3; c++) {
        const float* ew = (const float*)d_in[5 + 6 * c];
        const float* eb = (const float*)d_in[6 + 6 * c];
        const float* w1 = (const float*)d_in[7 + 6 * c];
        const float* b1 = (const float*)d_in[8 + 6 * c];
        const float* w2 = (const float*)d_in[9 + 6 * c];
        const float* b2 = (const float*)d_in[10 + 6 * c];

        copy_kernel<<<copy_blocks, 256>>>((float4*)agg, (const float4*)h, copy_n4);
        edge_scatter_kernel<<<sblocks, 128>>>(h, srcs, dsts, eas, ew, eb, agg, E);
        sgemm_kernel<true><<<gnode, 256>>>(agg, HID, w1, HID, b1, hid, HID, NN, HID);
        sgemm_kernel<true><<<gnode, 256>>>(hid, HID, w2, HID, b2, h, HID, NN, HID);
    }

    sgemm_kernel<false><<<gnode, 256>>>(h, HID, cls_w1, HID, nullptr, hid, HID, NN, HID);
    sgemm_kernel<false><<<gnode, 256>>>(h, HID, cls_w1 + 128 * HID, HID, nullptr, agg, HID, NN, HID);

    cls_fused_kernel<<<cblocks, 128>>>(hid, agg, src, dst, ea,
                                       cls_w1 + 256 * HID, cls_b1,
                                       cls_w2, cls_b2, (float*)d_out, E);
}

// round 7
// speedup vs baseline: 1.5053x; 1.3656x over previous
#include <cuda_runtime.h>
#include <cuda_bf16.h>
#include <cstdint>

#define N_NODES 100000
#define N_EDGES 600000
#define HID 128
#define OUT 24

// ---------------- scratch ----------------
__device__ float g_h  [(size_t)N_NODES * HID];
__device__ float g_agg[(size_t)N_NODES * HID];
__device__ float g_hid[(size_t)N_NODES * HID];

// ---------------- packed f32x2 helpers ----------------
__device__ __forceinline__ unsigned long long pk2(float lo, float hi) {
    unsigned long long r;
    asm("mov.b64 %0, {%1, %2};" : "=l"(r) : "f"(lo), "f"(hi));
    return r;
}
__device__ __forceinline__ void fma2(unsigned long long& d,
                                     unsigned long long a, unsigned long long b) {
    asm("fma.rn.f32x2 %0, %1, %2, %0;" : "+l"(d) : "l"(a), "l"(b));
}
__device__ __forceinline__ float2 upk(unsigned long long v) {
    float2 f;
    asm("mov.b64 {%0, %1}, %2;" : "=f"(f.x), "=f"(f.y) : "l"(v));
    return f;
}
__device__ __forceinline__ uint32_t f2tf32(float f) {
    uint32_t u;
    asm("cvt.rna.tf32.f32 %0, %1;" : "=r"(u) : "f"(f));
    return u;
}

// ---------------- tf32 tensor-core GEMM: C[M,128]=A[M,K]@W[K,128] ----------
// 256 threads = 8 warps (4 m-warps x 2 n-warps), warp tile 32x64,
// mma.sync.m16n8k8 tf32, fp32 accumulate. APAD=136 (mod32=8) makes all
// fragment LDS conflict-free.
#define BM 128
#define BN 128
#define BK 16
#define APAD 136

template<bool RELU>
__global__ __launch_bounds__(256)
void tgemm_kernel(const float* __restrict__ A, int lda,
                  const float* __restrict__ W, int ldw,
                  const float* __restrict__ bias,
                  float* __restrict__ C, int ldc,
                  int M, int K)
{
    __shared__ uint32_t As[BK][APAD];   // tf32 bits, [k][m]
    __shared__ uint32_t Ws[BK][APAD];   // tf32 bits, [k][n]

    const int tid  = threadIdx.x;
    const int m0   = blockIdx.y * BM;
    const int warp = tid >> 5;
    const int lane = tid & 31;
    const int g    = lane >> 2;
    const int tig  = lane & 3;
    const int wm   = (warp & 3) * 32;
    const int wn   = (warp >> 2) * 64;

    float acc[2][8][4];
    #pragma unroll
    for (int i = 0; i < 2; i++)
        #pragma unroll
        for (int j = 0; j < 8; j++)
            #pragma unroll
            for (int q = 0; q < 4; q++) acc[i][j][q] = 0.f;

    for (int k0 = 0; k0 < K; k0 += BK) {
        // A tile: 128 rows x 16 k, float4 along k, transposed into As[k][m]
        #pragma unroll
        for (int p = 0; p < 2; p++) {
            int idx = tid + p * 256;
            int m   = idx >> 2;
            int k4  = (idx & 3) << 2;
            float4 v = make_float4(0.f, 0.f, 0.f, 0.f);
            int gm = m0 + m;
            if (gm < M)
                v = *reinterpret_cast<const float4*>(A + (size_t)gm * lda + k0 + k4);
            As[k4 + 0][m] = f2tf32(v.x);
            As[k4 + 1][m] = f2tf32(v.y);
            As[k4 + 2][m] = f2tf32(v.z);
            As[k4 + 3][m] = f2tf32(v.w);
        }
        // W tile: 16 k x 128 n
        #pragma unroll
        for (int p = 0; p < 2; p++) {
            int idx = tid + p * 256;
            int k   = idx >> 5;
            int n4  = (idx & 31) << 2;
            float4 v = *reinterpret_cast<const float4*>(W + (size_t)(k0 + k) * ldw + n4);
            Ws[k][n4 + 0] = f2tf32(v.x);
            Ws[k][n4 + 1] = f2tf32(v.y);
            Ws[k][n4 + 2] = f2tf32(v.z);
            Ws[k][n4 + 3] = f2tf32(v.w);
        }
        __syncthreads();

        #pragma unroll
        for (int kk = 0; kk < BK; kk += 8) {
            uint32_t a[2][4];
            #pragma unroll
            for (int mf = 0; mf < 2; mf++) {
                a[mf][0] = As[kk + tig    ][wm + mf * 16 + g];
                a[mf][1] = As[kk + tig    ][wm + mf * 16 + g + 8];
                a[mf][2] = As[kk + tig + 4][wm + mf * 16 + g];
                a[mf][3] = As[kk + tig + 4][wm + mf * 16 + g + 8];
            }
            #pragma unroll
            for (int nf = 0; nf < 8; nf++) {
                uint32_t b0 = Ws[kk + tig    ][wn + nf * 8 + g];
                uint32_t b1 = Ws[kk + tig + 4][wn + nf * 8 + g];
                #pragma unroll
                for (int mf = 0; mf < 2; mf++) {
                    asm volatile(
                        "mma.sync.aligned.m16n8k8.row.col.f32.tf32.tf32.f32 "
                        "{%0,%1,%2,%3}, {%4,%5,%6,%7}, {%8,%9}, {%0,%1,%2,%3};"
                        : "+f"(acc[mf][nf][0]), "+f"(acc[mf][nf][1]),
                          "+f"(acc[mf][nf][2]), "+f"(acc[mf][nf][3])
                        : "r"(a[mf][0]), "r"(a[mf][1]), "r"(a[mf][2]), "r"(a[mf][3]),
                          "r"(b0), "r"(b1));
                }
            }
        }
        __syncthreads();
    }

    // epilogue: c0,c1 -> (row, col..col+1); c2,c3 -> (row+8, col..col+1)
    #pragma unroll
    for (int mf = 0; mf < 2; mf++) {
        int r0 = m0 + wm + mf * 16 + g;
        #pragma unroll
        for (int nf = 0; nf < 8; nf++) {
            int col = wn + nf * 8 + 2 * tig;
            float bv0 = bias ? bias[col]     : 0.f;
            float bv1 = bias ? bias[col + 1] : 0.f;
            float c0 = acc[mf][nf][0] + bv0, c1 = acc[mf][nf][1] + bv1;
            float c2 = acc[mf][nf][2] + bv0, c3 = acc[mf][nf][3] + bv1;
            if (RELU) {
                c0 = fmaxf(c0, 0.f); c1 = fmaxf(c1, 0.f);
                c2 = fmaxf(c2, 0.f); c3 = fmaxf(c3, 0.f);
            }
            if (r0 < M)
                *reinterpret_cast<float2*>(C + (size_t)r0 * ldc + col) = make_float2(c0, c1);
            if (r0 + 8 < M)
                *reinterpret_cast<float2*>(C + (size_t)(r0 + 8) * ldc + col) = make_float2(c2, c3);
        }
    }
}

// ---------------- copy kernel ----------------
__global__ void copy_kernel(float4* __restrict__ dst, const float4* __restrict__ src, int n4)
{
    int i = blockIdx.x * blockDim.x + threadIdx.x;
    if (i < n4) dst[i] = src[i];
}

// ---------------- fused edge-embedding + message + scatter (exact R2) ------
__global__ __launch_bounds__(128)
void edge_scatter_kernel(const float* __restrict__ h,
                         const int* __restrict__ src,
                         const int* __restrict__ dst,
                         const float* __restrict__ ea,
                         const float* __restrict__ ew,
                         const float* __restrict__ eb,
                         float* __restrict__ agg,
                         int E)
{
    __shared__ float ea_s[32][32];
    __shared__ int src_s[32];
    __shared__ int dst_s[32];

    const int d = threadIdx.x;
    unsigned long long wcol2[16];
    #pragma unroll
    for (int t = 0; t < 16; t++)
        wcol2[t] = pk2(ew[(2 * t) * HID + d], ew[(2 * t + 1) * HID + d]);
    const float bd = eb[d];

    const int base = blockIdx.x * 32;
    const int ne = min(32, E - base);
    if (ne <= 0) return;

    for (int idx = threadIdx.x; idx < ne * 32; idx += 128)
        ea_s[idx >> 5][idx & 31] = ea[(size_t)base * 32 + idx];
    if (threadIdx.x < ne) {
        src_s[threadIdx.x] = src[base + threadIdx.x];
        dst_s[threadIdx.x] = dst[base + threadIdx.x];
    }
    __syncthreads();

    float hs = h[(size_t)src_s[0] * HID + d];
    for (int e = 0; e < ne; e++) {
        float hs_next = 0.f;
        if (e + 1 < ne) hs_next = h[(size_t)src_s[e + 1] * HID + d];
        const unsigned long long* eav =
            reinterpret_cast<const unsigned long long*>(&ea_s[e][0]);
        unsigned long long ac0 = 0ull, ac1 = 0ull;
        #pragma unroll
        for (int t = 0; t < 8; t++) {
            fma2(ac0, eav[2 * t],     wcol2[2 * t]);
            fma2(ac1, eav[2 * t + 1], wcol2[2 * t + 1]);
        }
        float2 s0 = upk(ac0), s1 = upk(ac1);
        float v = fmaxf((s0.x + s0.y) + (s1.x + s1.y) + bd + hs, 0.f);
        atomicAdd(&agg[(size_t)dst_s[e] * HID + d], v);
        hs = hs_next;
    }
}

// ---------------- fused classifier (exact R2) ----------------
#define CLS_E 64
#define HPAD 132

__global__ __launch_bounds__(128)
void cls_fused_kernel(const float* __restrict__ P,
                      const float* __restrict__ Q,
                      const int* __restrict__ src,
                      const int* __restrict__ dst,
                      const float* __restrict__ ea,
                      const float* __restrict__ w1c,
                      const float* __restrict__ b1,
                      const float* __restrict__ w2,
                      const float* __restrict__ b2,
                      float* __restrict__ out,
                      int E)
{
    __shared__ float hid_s[CLS_E][HPAD];
    __shared__ float w2t[OUT][HPAD];
    __shared__ float ea_s[CLS_E][32];
    __shared__ int src_s[CLS_E];
    __shared__ int dst_s[CLS_E];

    const int tid = threadIdx.x;
    const int base = blockIdx.x * CLS_E;
    const int ne = min(CLS_E, E - base);
    if (ne <= 0) return;

    for (int idx = tid; idx < HID * OUT; idx += 128) {
        float v = w2[idx];
        w2t[idx % OUT][idx / OUT] = v;
    }
    for (int idx = tid; idx < ne * 32; idx += 128)
        ea_s[idx >> 5][idx & 31] = ea[(size_t)base * 32 + idx];
    if (tid < ne) {
        src_s[tid] = src[base + tid];
        dst_s[tid] = dst[base + tid];
    }
    __syncthreads();

    {
        const int d = tid;
        unsigned long long wcol2[16];
        #pragma unroll
        for (int t = 0; t < 16; t++)
            wcol2[t] = pk2(w1c[(2 * t) * HID + d], w1c[(2 * t + 1) * HID + d]);
        const float bd = b1[d];

        float pq = P[(size_t)src_s[0] * HID + d] + Q[(size_t)dst_s[0] * HID + d];
        for (int e = 0; e < ne; e++) {
            float pq_next = 0.f;
            if (e + 1 < ne)
                pq_next = P[(size_t)src_s[e + 1] * HID + d] +
                          Q[(size_t)dst_s[e + 1] * HID + d];
            const unsigned long long* eav =
                reinterpret_cast<const unsigned long long*>(&ea_s[e][0]);
            unsigned long long ac0 = 0ull, ac1 = 0ull;
            #pragma unroll
            for (int t = 0; t < 8; t++) {
                fma2(ac0, eav[2 * t],     wcol2[2 * t]);
                fma2(ac1, eav[2 * t + 1], wcol2[2 * t + 1]);
            }
            float2 s0 = upk(ac0), s1 = upk(ac1);
            hid_s[e][d] = fmaxf((s0.x + s0.y) + (s1.x + s1.y) + bd + pq, 0.f);
            pq = pq_next;
        }
    }
    __syncthreads();

    const int oq = tid & 7;
    const int eq = tid >> 3;
    const int o0 = oq * 3;
    const int e0 = eq * 4;

    unsigned long long acc2[4][3];
    #pragma unroll
    for (int i = 0; i < 4; i++)
        #pragma unroll
        for (int j = 0; j < 3; j++) acc2[i][j] = 0ull;

    #pragma unroll 4
    for (int dch = 0; dch < HID; dch += 4) {
        unsigned long long h2[4][2], w2r[3][2];
        #pragma unroll
        for (int i = 0; i < 4; i++) {
            const unsigned long long* hp =
                reinterpret_cast<const unsigned long long*>(&hid_s[e0 + i][dch]);
            h2[i][0] = hp[0]; h2[i][1] = hp[1];
        }
        #pragma unroll
        for (int j = 0; j < 3; j++) {
            const unsigned long long* wp =
                reinterpret_cast<const unsigned long long*>(&w2t[o0 + j][dch]);
            w2r[j][0] = wp[0]; w2r[j][1] = wp[1];
        }
        #pragma unroll
        for (int i = 0; i < 4; i++)
            #pragma unroll
            for (int j = 0; j < 3; j++) {
                fma2(acc2[i][j], h2[i][0], w2r[j][0]);
                fma2(acc2[i][j], h2[i][1], w2r[j][1]);
            }
    }

    #pragma unroll
    for (int i = 0; i < 4; i++) {
        int e = e0 + i;
        if (e >= ne) continue;
        #pragma unroll
        for (int j = 0; j < 3; j++) {
            float2 s = upk(acc2[i][j]);
            out[(size_t)(base + e) * OUT + o0 + j] = s.x + s.y + b2[o0 + j];
        }
    }
}

// ---------------- host ----------------
extern "C" void kernel_launch(void* const* d_in, const int* in_sizes, int n_in,
                              void* d_out, int out_size)
{
    const float* x      = (const float*)d_in[0];
    const int*   eidx   = (const int*)  d_in[1];
    const float* ea     = (const float*)d_in[2];
    const float* lin1_w = (const float*)d_in[3];
    const float* lin1_b = (const float*)d_in[4];
    const float* cls_w1 = (const float*)d_in[23];
    const float* cls_b1 = (const float*)d_in[24];
    const float* cls_w2 = (const float*)d_in[25];
    const float* cls_b2 = (const float*)d_in[26];

    const int NN = in_sizes[0] / 64;
    const int E  = in_sizes[2] / 32;
    const int* src = eidx;
    const int* dst = eidx + E;

    float *h, *agg, *hid;
    cudaGetSymbolAddress((void**)&h,   g_h);
    cudaGetSymbolAddress((void**)&agg, g_agg);
    cudaGetSymbolAddress((void**)&hid, g_hid);

    const dim3 gnode(1, (unsigned)((NN + BM - 1) / BM));
    const int sblocks = (E + 31) / 32;
    const int cblocks = (E + CLS_E - 1) / CLS_E;
    const int copy_n4 = (NN * HID) / 4;
    const int copy_blocks = (copy_n4 + 255) / 256;

    tgemm_kernel<false><<<gnode, 256>>>(x, 64, lin1_w, HID, lin1_b, h, HID, NN, 64);

    for (int c = 0; c < 3; c++) {
        const float* ew = (const float*)d_in[5 + 6 * c];
        const float* eb = (const float*)d_in[6 + 6 * c];
        const float* w1 = (const float*)d_in[7 + 6 * c];
        const float* b1 = (const float*)d_in[8 + 6 * c];
        const float* w2 = (const float*)d_in[9 + 6 * c];
        const float* b2 = (const float*)d_in[10 + 6 * c];

        copy_kernel<<<copy_blocks, 256>>>((float4*)agg, (const float4*)h, copy_n4);
        edge_scatter_kernel<<<sblocks, 128>>>(h, src, dst, ea, ew, eb, agg, E);
        tgemm_kernel<true><<<gnode, 256>>>(agg, HID, w1, HID, b1, hid, HID, NN, HID);
        tgemm_kernel<true><<<gnode, 256>>>(hid, HID, w2, HID, b2, h, HID, NN, HID);
    }

    tgemm_kernel<false><<<gnode, 256>>>(h, HID, cls_w1, HID, nullptr, hid, HID, NN, HID);
    tgemm_kernel<false><<<gnode, 256>>>(h, HID, cls_w1 + 128 * HID, HID, nullptr, agg, HID, NN, HID);

    cls_fused_kernel<<<cblocks, 128>>>(hid, agg, src, dst, ea,
                                       cls_w1 + 256 * HID, cls_b1,
                                       cls_w2, cls_b2, (float*)d_out, E);
}